// round 4
// baseline (speedup 1.0000x reference)
#include <cuda_runtime.h>
#include <math.h>
#include <float.h>

#define N      1024
#define FIN    512
#define FOUT   128
#define NT     16     // j-tiles of 64

// Scratch (no allocations allowed)
__device__ float g_h[N * FOUT];      // embedding
__device__ float g_n[N];             // row squared norms
__device__ float g_ppos[NT * N];     // per-j-tile partial max of (n_j - 2*dot)
__device__ float g_pneg[NT * N];     // per-j-tile partial min

// ---------------------------------------------------------------------------
// K1: h = inp @ W + b, plus row norms. Block = 256 thr (32 f-quads x 8 rows).
// ---------------------------------------------------------------------------
__global__ __launch_bounds__(256) void k_linear(
    const float* __restrict__ inp, const float* __restrict__ W,
    const float* __restrict__ b) {
  __shared__ __align__(16) float sIn[8][FIN];
  const int tx = threadIdx.x & 31;   // f-quad index (0..31) -> cols tx*4..tx*4+3
  const int ty = threadIdx.x >> 5;   // row within block (0..7) == warp id
  const int row0 = blockIdx.x * 8;

  // stage 8x512 input rows: 1024 float4 / 256 threads = 4 each
  const float4* gi4 = (const float4*)(inp + (size_t)row0 * FIN);
  float4* s4 = (float4*)&sIn[0][0];
#pragma unroll
  for (int t = 0; t < 4; t++) s4[threadIdx.x + t * 256] = gi4[threadIdx.x + t * 256];
  __syncthreads();

  float a0 = 0.f, a1 = 0.f, a2 = 0.f, a3 = 0.f;
  const float4* W4 = (const float4*)W;
#pragma unroll 4
  for (int k = 0; k < FIN; k++) {
    float4 w = W4[k * (FOUT / 4) + tx];
    float a = sIn[ty][k];            // broadcast within warp
    a0 += a * w.x; a1 += a * w.y; a2 += a * w.z; a3 += a * w.w;
  }
  float4 bb = ((const float4*)b)[tx];
  a0 += bb.x; a1 += bb.y; a2 += bb.z; a3 += bb.w;

  const int row = row0 + ty;
  ((float4*)g_h)[row * (FOUT / 4) + tx] = make_float4(a0, a1, a2, a3);

  float s = a0 * a0 + a1 * a1 + a2 * a2 + a3 * a3;
#pragma unroll
  for (int off = 16; off; off >>= 1) s += __shfl_xor_sync(0xffffffffu, s, off);
  if (tx == 0) g_n[row] = s;
}

// ---------------------------------------------------------------------------
// K2: fused Gram tile + hardest-pos/neg reduction.
// Tile 64(i) x 64(j), grid (16,16), block 256 = 16(tx:j) x 16(ty:i), micro 4x4.
// f chunked in 2 halves of 64 to fit 48KB static smem (transposed layout).
// ---------------------------------------------------------------------------
__global__ __launch_bounds__(256) void k_dist(const int* __restrict__ targets) {
  __shared__ __align__(16) float sA[64][68];  // [f_local][i_local], pad 68
  __shared__ __align__(16) float sB[64][68];  // [f_local][j_local]
  __shared__ float sNB[64];
  __shared__ int sTA[64], sTB[64];

  const int tid = threadIdx.x;
  const int tx = tid & 15;           // j micro position
  const int ty = tid >> 4;           // i micro position
  const int j0 = blockIdx.x * 64;
  const int i0 = blockIdx.y * 64;

  if (tid < 64) {
    sNB[tid] = g_n[j0 + tid];
    sTA[tid] = targets[i0 + tid];
    sTB[tid] = targets[j0 + tid];
  }

  float acc[4][4];
#pragma unroll
  for (int ii = 0; ii < 4; ii++)
#pragma unroll
    for (int jj = 0; jj < 4; jj++) acc[ii][jj] = 0.f;

  const int lr = tid >> 2;  // row 0..63 for staging loads
  const int lq = tid & 3;   // quad group

  for (int kc = 0; kc < 2; kc++) {
    __syncthreads();  // smem reuse barrier (also orders sNB/sTA/sTB writes)
#pragma unroll
    for (int l = 0; l < 4; l++) {
      int q = lq + l * 4;  // 0..15 (float4 index within 64-float chunk)
      float4 va = ((const float4*)g_h)[(i0 + lr) * (FOUT / 4) + kc * 16 + q];
      sA[q * 4 + 0][lr] = va.x; sA[q * 4 + 1][lr] = va.y;
      sA[q * 4 + 2][lr] = va.z; sA[q * 4 + 3][lr] = va.w;
      float4 vb = ((const float4*)g_h)[(j0 + lr) * (FOUT / 4) + kc * 16 + q];
      sB[q * 4 + 0][lr] = vb.x; sB[q * 4 + 1][lr] = vb.y;
      sB[q * 4 + 2][lr] = vb.z; sB[q * 4 + 3][lr] = vb.w;
    }
    __syncthreads();

#pragma unroll 8
    for (int f = 0; f < 64; f++) {
      float4 av = *(const float4*)&sA[f][ty * 4];
      float4 bv = *(const float4*)&sB[f][tx * 4];
      float ar[4] = {av.x, av.y, av.z, av.w};
      float br[4] = {bv.x, bv.y, bv.z, bv.w};
#pragma unroll
      for (int ii = 0; ii < 4; ii++)
#pragma unroll
        for (int jj = 0; jj < 4; jj++) acc[ii][jj] += ar[ii] * br[jj];
    }
  }

  // Epilogue: v = n_j - 2*dot; masked max (pos, j!=i) / min (neg).
#pragma unroll
  for (int ii = 0; ii < 4; ii++) {
    const int i_l = ty * 4 + ii;
    const int gi = i0 + i_l;
    const int ti = sTA[i_l];
    float pmax = -FLT_MAX, nmin = FLT_MAX;
#pragma unroll
    for (int jj = 0; jj < 4; jj++) {
      const int j_l = tx * 4 + jj;
      const int gj = j0 + j_l;
      float v = sNB[j_l] - 2.f * acc[ii][jj];
      bool same = (ti == sTB[j_l]);
      if (same) {
        if (gi != gj) pmax = fmaxf(pmax, v);
      } else {
        nmin = fminf(nmin, v);
      }
    }
    // reduce across tx (16 lanes sharing this i)
#pragma unroll
    for (int off = 8; off; off >>= 1) {
      pmax = fmaxf(pmax, __shfl_xor_sync(0xffffffffu, pmax, off));
      nmin = fminf(nmin, __shfl_xor_sync(0xffffffffu, nmin, off));
    }
    if (tx == 0) {
      g_ppos[blockIdx.x * N + gi] = pmax;
      g_pneg[blockIdx.x * N + gi] = nmin;
    }
  }
}

// ---------------------------------------------------------------------------
// K3: finalize. Merge 16 j-tile partials, sqrt, softplus, sum -> out[0].
// ---------------------------------------------------------------------------
__global__ __launch_bounds__(1024) void k_final(float* __restrict__ out) {
  const int i = threadIdx.x;
  float pmax = -FLT_MAX, nmin = FLT_MAX;
#pragma unroll
  for (int t = 0; t < NT; t++) {
    pmax = fmaxf(pmax, g_ppos[t * N + i]);
    nmin = fminf(nmin, g_pneg[t * N + i]);
  }
  const float ni = g_n[i];
  const bool haspos = (pmax > -FLT_MAX);
  const bool hasneg = (nmin < FLT_MAX);
  float sp = 0.f;  // softplus(-inf) = 0 when no positive exists
  if (haspos) {
    float hp = sqrtf(fmaxf(ni + pmax, 0.f));
    if (hasneg) {
      float hn = sqrtf(fmaxf(ni + nmin, 0.f));
      float x = hp - hn;
      sp = fmaxf(x, 0.f) + log1pf(expf(-fabsf(x)));
    } else {
      sp = INFINITY;  // softplus(+inf)
    }
  }

  // block sum of 1024 values
  __shared__ float wsum[32];
  float s = sp;
#pragma unroll
  for (int off = 16; off; off >>= 1) s += __shfl_xor_sync(0xffffffffu, s, off);
  if ((i & 31) == 0) wsum[i >> 5] = s;
  __syncthreads();
  if (i < 32) {
    float t = wsum[i];
#pragma unroll
    for (int off = 16; off; off >>= 1) t += __shfl_xor_sync(0xffffffffu, t, off);
    if (i == 0) out[0] = t;
  }
}

// ---------------------------------------------------------------------------
extern "C" void kernel_launch(void* const* d_in, const int* in_sizes, int n_in,
                              void* d_out, int out_size) {
  const float* inp     = (const float*)d_in[0];
  const int*   targets = (const int*)d_in[1];
  const float* W       = (const float*)d_in[2];
  const float* b       = (const float*)d_in[3];
  float* out = (float*)d_out;

  k_linear<<<N / 8, 256>>>(inp, W, b);
  k_dist<<<dim3(NT, NT), 256>>>(targets);
  k_final<<<1, 1024>>>(out);
}

// round 5
// speedup vs baseline: 2.5390x; 2.5390x over previous
#include <cuda_runtime.h>
#include <math.h>
#include <float.h>

#define N      1024
#define FIN    512
#define FOUT   128
#define NT     16     // j-tiles of 64 (K2)
#define KSLICE 8      // K-split for K1
#define KC     (FIN / KSLICE)   // 64 k per slice
#define SUB    32     // k subchunk staged in smem

// Scratch (no allocations allowed)
__device__ float g_part[KSLICE][N][FOUT];  // K1 partial sums (4MB)
__device__ float g_h[N * FOUT];            // embedding
__device__ float g_n[N];                   // row squared norms
__device__ float g_ppos[NT * N];           // per-j-tile partial max of (n_j - 2*dot)
__device__ float g_pneg[NT * N];           // per-j-tile partial min

// ---------------------------------------------------------------------------
// K1a: K-split GEMM. Block tile 64(m) x 128(n) x 64(k-slice).
// Grid (16 m-tiles, 8 k-slices) = 128 blocks. 256 thr, micro 8x4.
// Per f-iter: 1 LDS.128 (W) + 2 LDS.128 broadcast (A) + 32 FFMA.
// ---------------------------------------------------------------------------
__global__ __launch_bounds__(256) void k_gemm(
    const float* __restrict__ inp, const float* __restrict__ W) {
  __shared__ __align__(16) float sA[SUB][68];   // [k][row] transposed, pad 68
  __shared__ __align__(16) float sW[SUB][FOUT]; // [k][col]

  const int tid = threadIdx.x;
  const int tx = tid & 31;     // col quad (0..31) -> cols tx*4..+3
  const int ty = tid >> 5;     // row octet (0..7) -> rows ty*8..+7
  const int m0 = blockIdx.x * 64;
  const int k0 = blockIdx.y * KC;

  float acc[8][4];
#pragma unroll
  for (int r = 0; r < 8; r++)
#pragma unroll
    for (int c = 0; c < 4; c++) acc[r][c] = 0.f;

  for (int sc = 0; sc < KC / SUB; sc++) {
    const int kb = k0 + sc * SUB;
    __syncthreads();
    // stage A transposed: 64 rows x 32 k = 512 float4, 2 per thread
#pragma unroll
    for (int it = 0; it < 2; it++) {
      int idx = tid + it * 256;
      int row = idx >> 3;            // 0..63
      int q = idx & 7;               // k-quad 0..7
      float4 v = *(const float4*)(inp + (size_t)(m0 + row) * FIN + kb + q * 4);
      sA[q * 4 + 0][row] = v.x; sA[q * 4 + 1][row] = v.y;
      sA[q * 4 + 2][row] = v.z; sA[q * 4 + 3][row] = v.w;
    }
    // stage W direct: 32 k x 128 cols = 1024 float4, 4 per thread
#pragma unroll
    for (int it = 0; it < 4; it++) {
      int idx = tid + it * 256;
      int kk = idx >> 5;             // 0..31
      int cq = idx & 31;             // col quad
      ((float4*)&sW[kk][0])[cq] = *(const float4*)(W + (size_t)(kb + kk) * FOUT + cq * 4);
    }
    __syncthreads();

#pragma unroll 8
    for (int k = 0; k < SUB; k++) {
      float4 w  = *(const float4*)&sW[k][tx * 4];
      float4 a0 = *(const float4*)&sA[k][ty * 8];      // broadcast in warp
      float4 a1 = *(const float4*)&sA[k][ty * 8 + 4];  // broadcast in warp
      float ar[8] = {a0.x, a0.y, a0.z, a0.w, a1.x, a1.y, a1.z, a1.w};
      float wr[4] = {w.x, w.y, w.z, w.w};
#pragma unroll
      for (int r = 0; r < 8; r++)
#pragma unroll
        for (int c = 0; c < 4; c++) acc[r][c] += ar[r] * wr[c];
    }
  }

#pragma unroll
  for (int r = 0; r < 8; r++) {
    *(float4*)&g_part[blockIdx.y][m0 + ty * 8 + r][tx * 4] =
        make_float4(acc[r][0], acc[r][1], acc[r][2], acc[r][3]);
  }
}

// ---------------------------------------------------------------------------
// K1b: reduce 8 K-slices + bias -> h, plus row squared norms.
// Grid 1024 (one row per block), 128 threads (one col each).
// ---------------------------------------------------------------------------
__global__ __launch_bounds__(128) void k_reduce(const float* __restrict__ b) {
  const int row = blockIdx.x;
  const int col = threadIdx.x;
  float s = b[col];
#pragma unroll
  for (int t = 0; t < KSLICE; t++) s += g_part[t][row][col];
  g_h[row * FOUT + col] = s;

  float sq = s * s;
#pragma unroll
  for (int off = 16; off; off >>= 1) sq += __shfl_xor_sync(0xffffffffu, sq, off);
  __shared__ float ws[4];
  if ((col & 31) == 0) ws[col >> 5] = sq;
  __syncthreads();
  if (col == 0) g_n[row] = ws[0] + ws[1] + ws[2] + ws[3];
}

// ---------------------------------------------------------------------------
// K2: fused Gram tile + hardest-pos/neg reduction.
// Tile 64(i) x 64(j), grid (16,16), block 256 = 16(tx:j) x 16(ty:i), micro 4x4.
// ---------------------------------------------------------------------------
__global__ __launch_bounds__(256) void k_dist(const int* __restrict__ targets) {
  __shared__ __align__(16) float sA[64][68];  // [f_local][i_local], pad 68
  __shared__ __align__(16) float sB[64][68];  // [f_local][j_local]
  __shared__ float sNB[64];
  __shared__ int sTA[64], sTB[64];

  const int tid = threadIdx.x;
  const int tx = tid & 15;           // j micro position
  const int ty = tid >> 4;           // i micro position
  const int j0 = blockIdx.x * 64;
  const int i0 = blockIdx.y * 64;

  if (tid < 64) {
    sNB[tid] = g_n[j0 + tid];
    sTA[tid] = targets[i0 + tid];
    sTB[tid] = targets[j0 + tid];
  }

  float acc[4][4];
#pragma unroll
  for (int ii = 0; ii < 4; ii++)
#pragma unroll
    for (int jj = 0; jj < 4; jj++) acc[ii][jj] = 0.f;

  const int lr = tid >> 2;  // row 0..63 for staging loads
  const int lq = tid & 3;   // quad group

  for (int kc = 0; kc < 2; kc++) {
    __syncthreads();  // smem reuse barrier (also orders sNB/sTA/sTB writes)
#pragma unroll
    for (int l = 0; l < 4; l++) {
      int q = lq + l * 4;  // 0..15 (float4 index within 64-float chunk)
      float4 va = ((const float4*)g_h)[(i0 + lr) * (FOUT / 4) + kc * 16 + q];
      sA[q * 4 + 0][lr] = va.x; sA[q * 4 + 1][lr] = va.y;
      sA[q * 4 + 2][lr] = va.z; sA[q * 4 + 3][lr] = va.w;
      float4 vb = ((const float4*)g_h)[(j0 + lr) * (FOUT / 4) + kc * 16 + q];
      sB[q * 4 + 0][lr] = vb.x; sB[q * 4 + 1][lr] = vb.y;
      sB[q * 4 + 2][lr] = vb.z; sB[q * 4 + 3][lr] = vb.w;
    }
    __syncthreads();

#pragma unroll 8
    for (int f = 0; f < 64; f++) {
      float4 av = *(const float4*)&sA[f][ty * 4];
      float4 bv = *(const float4*)&sB[f][tx * 4];
      float ar[4] = {av.x, av.y, av.z, av.w};
      float br[4] = {bv.x, bv.y, bv.z, bv.w};
#pragma unroll
      for (int ii = 0; ii < 4; ii++)
#pragma unroll
        for (int jj = 0; jj < 4; jj++) acc[ii][jj] += ar[ii] * br[jj];
    }
  }

  // Epilogue: v = n_j - 2*dot; masked max (pos, j!=i) / min (neg).
#pragma unroll
  for (int ii = 0; ii < 4; ii++) {
    const int i_l = ty * 4 + ii;
    const int gi = i0 + i_l;
    const int ti = sTA[i_l];
    float pmax = -FLT_MAX, nmin = FLT_MAX;
#pragma unroll
    for (int jj = 0; jj < 4; jj++) {
      const int j_l = tx * 4 + jj;
      const int gj = j0 + j_l;
      float v = sNB[j_l] - 2.f * acc[ii][jj];
      bool same = (ti == sTB[j_l]);
      if (same) {
        if (gi != gj) pmax = fmaxf(pmax, v);
      } else {
        nmin = fminf(nmin, v);
      }
    }
    // reduce across tx (16 lanes sharing this i)
#pragma unroll
    for (int off = 8; off; off >>= 1) {
      pmax = fmaxf(pmax, __shfl_xor_sync(0xffffffffu, pmax, off));
      nmin = fminf(nmin, __shfl_xor_sync(0xffffffffu, nmin, off));
    }
    if (tx == 0) {
      g_ppos[blockIdx.x * N + gi] = pmax;
      g_pneg[blockIdx.x * N + gi] = nmin;
    }
  }
}

// ---------------------------------------------------------------------------
// K3: finalize. Merge 16 j-tile partials, sqrt, softplus, sum -> out[0].
// ---------------------------------------------------------------------------
__global__ __launch_bounds__(1024) void k_final(float* __restrict__ out) {
  const int i = threadIdx.x;
  float pmax = -FLT_MAX, nmin = FLT_MAX;
#pragma unroll
  for (int t = 0; t < NT; t++) {
    pmax = fmaxf(pmax, g_ppos[t * N + i]);
    nmin = fminf(nmin, g_pneg[t * N + i]);
  }
  const float ni = g_n[i];
  const bool haspos = (pmax > -FLT_MAX);
  const bool hasneg = (nmin < FLT_MAX);
  float sp = 0.f;  // softplus(-inf) = 0 when no positive exists
  if (haspos) {
    float hp = sqrtf(fmaxf(ni + pmax, 0.f));
    if (hasneg) {
      float hn = sqrtf(fmaxf(ni + nmin, 0.f));
      float x = hp - hn;
      sp = fmaxf(x, 0.f) + log1pf(expf(-fabsf(x)));
    } else {
      sp = INFINITY;  // softplus(+inf)
    }
  }

  // block sum of 1024 values
  __shared__ float wsum[32];
  float s = sp;
#pragma unroll
  for (int off = 16; off; off >>= 1) s += __shfl_xor_sync(0xffffffffu, s, off);
  if ((i & 31) == 0) wsum[i >> 5] = s;
  __syncthreads();
  if (i < 32) {
    float t = wsum[i];
#pragma unroll
    for (int off = 16; off; off >>= 1) t += __shfl_xor_sync(0xffffffffu, t, off);
    if (i == 0) out[0] = t;
  }
}

// ---------------------------------------------------------------------------
extern "C" void kernel_launch(void* const* d_in, const int* in_sizes, int n_in,
                              void* d_out, int out_size) {
  const float* inp     = (const float*)d_in[0];
  const int*   targets = (const int*)d_in[1];
  const float* W       = (const float*)d_in[2];
  const float* b       = (const float*)d_in[3];
  float* out = (float*)d_out;

  k_gemm<<<dim3(16, KSLICE), 256>>>(inp, W);
  k_reduce<<<N, 128>>>(b);
  k_dist<<<dim3(NT, NT), 256>>>(targets);
  k_final<<<1, 1024>>>(out);
}